// round 15
// baseline (speedup 1.0000x reference)
#include <cuda_runtime.h>

#define BATCH 8
typedef unsigned long long ull;

// Inter-kernel scratch (no allocations allowed). These symbols are ONLY
// referenced from device code — passing a __device__ symbol as a host-side
// kernel argument yields the host shadow address (the R5 bug).
__device__ float g_hidden[BATCH * 8192];             // [batch][8192]
__device__ float g_part[16 * BATCH * 8192];          // [split][batch][row], 4 MB
__device__ int   g_ctr1[256];                         // k1 per-row-tile arrival counters
__device__ int   g_ctr2[64];                          // k2 per-row-tile arrival counters

__device__ __forceinline__ void fma2(ull &acc, ull a, ull b) {
    // packed fp32x2 FMA (Blackwell): acc.lo += a.lo*b.lo; acc.hi += a.hi*b.hi
    asm volatile("fma.rn.f32x2 %0, %1, %2, %0;" : "+l"(acc) : "l"(a), "l"(b));
}

// duplicate one fp32 into both halves of an f32x2 register pair
__device__ __forceinline__ ull dupf(unsigned w) {
    ull d;
    asm("mov.b64 %0, {%1, %1};" : "=l"(d) : "r"(w));
    return d;
}

// 1-bit XOR swizzle: makes the mainloop's 32B-strided LDS.128 input pattern
// conflict-free (each 8-lane phase covers all 32 banks). 16B-granular.
__device__ __forceinline__ int swz(int off) {
    return off ^ ((off >> 3) & 0x10);
}

__device__ __forceinline__ unsigned smem_u32(const void* p) {
    return (unsigned)__cvta_generic_to_shared(p);
}

// streaming global->smem 16B copy, L1-bypass (.cg)
__device__ __forceinline__ void cp_async16_cg(unsigned dst, const void* src) {
    asm volatile("cp.async.cg.shared.global [%0], [%1], 16;" :: "r"(dst), "l"(src) : "memory");
}

// wait until at most n cp.async groups are pending (immediate-operand dispatch)
__device__ __forceinline__ void wait_pending(int n) {
    if (n <= 0)      asm volatile("cp.async.wait_group 0;" ::: "memory");
    else if (n == 1) asm volatile("cp.async.wait_group 1;" ::: "memory");
    else if (n == 2) asm volatile("cp.async.wait_group 2;" ::: "memory");
    else             asm volatile("cp.async.wait_group 3;" ::: "memory");
}

// Split-K GEMV. Mainloop has ZERO block-wide barriers; each warp streams its
// weight tiles through a PRIVATE NS-stage smem ring via cp.async.cg (depth
// decoupled from registers: ~8 KB in flight per warp in steady state).
// Inputs for the block's KC range are staged once, batch-pair interleaved.
//   acc[r][p] = f32x2 accumulator for (row r, batches 2p/2p+1).
//   partial[(y*BATCH+b)*ROWS + row] = sum_{k in split y} W[row,k]*in[b,k]
//   Last arriving split block per row tile sums partials in fixed order
//   (deterministic), adds bias, optional tanh, writes dst[b*ROWS + row].
// in = concat(inA [BATCH, splitK], inB [BATCH, KFULL-splitK]); inA==nullptr -> g_hidden.
// Grid: x = row tiles (ROWS/(RPW*WARPS)), y = split, SPLITS = KFULL/KC.
template<int KFULL, int KC, int RPW, int WARPS, int NS, int ROWS, bool TANH>
__global__ void __launch_bounds__(WARPS * 32, 2) gemv_fused_kernel(
    const float* __restrict__ W,
    const float* __restrict__ inA,
    const float* __restrict__ inB,
    int splitK,
    const float* __restrict__ bias,
    float* __restrict__ outArg)
{
    constexpr int RPB    = RPW * WARPS;            // rows per block
    constexpr int SPLITS = KFULL / KC;
    constexpr int STEPS  = KC / 128;               // 128 k per warp per step
    constexpr int NPAIR  = BATCH / 2;              // 4 batch pairs
    static_assert(RPW * BATCH == 32, "one lane per (row,batch) output");
    static_assert(RPB * BATCH == WARPS * 32, "one thread per (row,batch) in epilogue");

    // Dynamic smem: [inputs: NPAIR*KC*2 floats][weight rings: WARPS*NS*RPW*128 floats]
    extern __shared__ float smem[];
    float* s_in = smem;                            // pair-interleaved inputs
    float* s_w  = smem + NPAIR * KC * 2;           // per-warp weight rings
    __shared__ int s_last;

    const int tid  = threadIdx.x;
    const int lane = tid & 31;
    const int warp = tid >> 5;
    const int row0 = blockIdx.x * RPB + warp * RPW;
    const int koff = blockIdx.y * KC;

    const float* srcA = inA ? inA : (const float*)g_hidden;

    // ---- One-time input staging: LDG two batch rows, STS interleaved ----
    {
        constexpr int NU = NPAIR * (KC / 4);       // units of (pair, 4 k)
        char* sbytes = (char*)s_in;
        #pragma unroll
        for (int u = tid; u < NU; u += WARPS * 32) {
            int p  = u / (KC / 4);
            int kl = (u % (KC / 4)) * 4;           // local k, 4-aligned
            int kg = koff + kl;
            const float* s0;
            const float* s1;
            if (kg < splitK) {
                s0 = srcA + (size_t)(2 * p)     * splitK + kg;
                s1 = srcA + (size_t)(2 * p + 1) * splitK + kg;
            } else {
                s0 = inB + (size_t)(2 * p)     * (KFULL - splitK) + (kg - splitK);
                s1 = inB + (size_t)(2 * p + 1) * (KFULL - splitK) + (kg - splitK);
            }
            float4 a = *(const float4*)s0;
            float4 b = *(const float4*)s1;
            char* base = sbytes + (size_t)p * (KC * 8);
            *(float4*)(base + swz(kl * 8))      = make_float4(a.x, b.x, a.y, b.y);
            *(float4*)(base + swz(kl * 8 + 16)) = make_float4(a.z, b.z, a.w, b.w);
        }
        __syncthreads();                           // the only block-wide barrier
    }

    // ---- Barrier-free mainloop: per-warp NS-stage cp.async weight ring ----
    ull acc[RPW][NPAIR];
    #pragma unroll
    for (int r = 0; r < RPW; r++)
        #pragma unroll
        for (int p = 0; p < NPAIR; p++)
            acc[r][p] = 0ull;

    // lane owns 4 CONSECUTIVE k: cp.async fetches are coalesced 512B/row/warp,
    // ring LDS.128 reads are contiguous 16B/lane (conflict-free).
    float* wring = s_w + (size_t)warp * (NS * RPW * 128);
    const float* wsrc = W + (size_t)row0 * KFULL + koff + lane * 4;

    auto issue_stage = [&](int slot, int s) {
        float* dst = wring + slot * (RPW * 128) + lane * 4;
        const float* src = wsrc + (size_t)s * 128;
        #pragma unroll
        for (int r = 0; r < RPW; r++)
            cp_async16_cg(smem_u32(dst + r * 128), src + (size_t)r * KFULL);
        asm volatile("cp.async.commit_group;" ::: "memory");
    };

    #pragma unroll
    for (int i = 0; i < NS - 1 && i < STEPS; i++)  // prologue: fill NS-1 stages
        issue_stage(i, i);

    const char* sbytes = (const char*)s_in;

    #pragma unroll
    for (int s = 0; s < STEPS; s++) {
        // stage s's group is complete when at most (newer groups) remain pending
        wait_pending(NS - 2 < STEPS - 1 - s ? NS - 2 : STEPS - 1 - s);

        const int slot = s % NS;
        uint4 w[RPW];
        #pragma unroll
        for (int r = 0; r < RPW; r++)
            w[r] = *(const uint4*)(wring + slot * (RPW * 128) + r * 128 + lane * 4);

        const int kk = s * 128 + lane * 4;         // element index of lane's k0
        ulonglong2 ivA[NPAIR], ivB[NPAIR];
        #pragma unroll
        for (int p = 0; p < NPAIR; p++) {
            const char* base = sbytes + (size_t)p * (KC * 8);
            ivA[p] = *(const ulonglong2*)(base + swz(kk * 8));        // batches, k0,k1
            ivB[p] = *(const ulonglong2*)(base + swz(kk * 8 + 16));   // batches, k2,k3
        }
        #pragma unroll
        for (int r = 0; r < RPW; r++) {
            ull d0 = dupf(w[r].x), d1 = dupf(w[r].y), d2 = dupf(w[r].z), d3 = dupf(w[r].w);
            #pragma unroll
            for (int p = 0; p < NPAIR; p++) {
                fma2(acc[r][p], d0, ivA[p].x);
                fma2(acc[r][p], d1, ivA[p].y);
                fma2(acc[r][p], d2, ivB[p].x);
                fma2(acc[r][p], d3, ivB[p].y);
            }
        }

        if (s + NS - 1 < STEPS)                    // refill: reuse distance = NS
            issue_stage((s + NS - 1) % NS, s + NS - 1);
    }

    // Cross-lane reduce: lane (r*8+b) ends owning partial (row0+r, batch b).
    float myval = 0.f;
    #pragma unroll
    for (int r = 0; r < RPW; r++) {
        #pragma unroll
        for (int b = 0; b < BATCH; b++) {
            ull a = acc[r][b >> 1];
            float v = (b & 1) ? __uint_as_float((unsigned)(a >> 32))
                              : __uint_as_float((unsigned)(a & 0xffffffffu));
            #pragma unroll
            for (int off = 16; off; off >>= 1)
                v += __shfl_xor_sync(0xffffffffu, v, off);
            if (lane == r * BATCH + b) myval = v;
        }
    }
    {
        const int r   = lane / BATCH;
        const int b   = lane % BATCH;
        const int row = row0 + r;
        g_part[((size_t)blockIdx.y * BATCH + b) * ROWS + row] = myval;
    }

    // ---- Fused epilogue: last split block for this row tile finishes the sum ----
    __threadfence();          // release: make this block's partials visible
    __syncthreads();          // all partials of this block written before the count
    int* ctr = TANH ? g_ctr1 : g_ctr2;
    if (tid == 0) {
        int old = atomicAdd(&ctr[blockIdx.x], 1);
        s_last = (old == SPLITS - 1);
    }
    __syncthreads();
    if (s_last) {
        __threadfence();      // acquire: see all other splits' partials
        // thread tid -> (row = base + tid/8, batch = tid%8)
        const int r   = tid >> 3;
        const int b   = tid & 7;
        const int row = blockIdx.x * RPB + r;
        float v = bias[row];
        #pragma unroll
        for (int s = 0; s < SPLITS; s++)              // fixed order -> deterministic
            v += g_part[((size_t)s * BATCH + b) * ROWS + row];
        if (TANH) v = tanhf(v);
        float* dst = TANH ? (float*)g_hidden : outArg;
        dst[(size_t)b * ROWS + row] = v;
        if (tid == 0) ctr[blockIdx.x] = 0;            // reset for next graph replay
    }
}

extern "C" void kernel_launch(void* const* d_in, const int* in_sizes, int n_in,
                              void* d_out, int out_size) {
    const float* x     = (const float*)d_in[0];   // [8, 8192]
    const float* h0    = (const float*)d_in[1];   // [8, 8192]
    const float* w_i2h = (const float*)d_in[2];   // [8192, 16384]
    const float* b_i2h = (const float*)d_in[3];   // [8192]
    const float* w_h2o = (const float*)d_in[4];   // [2048, 8192]
    const float* b_h2o = (const float*)d_in[5];   // [2048]
    float* out = (float*)d_out;                   // [8, 2048]

    // smem: inputs (NPAIR*KC*2 floats) + rings (WARPS*NS*RPW*128 floats)
    constexpr int SMEM1 = (4 * 1024 * 2 + 8 * 5 * 4 * 128) * 4;   // 114688 B
    constexpr int SMEM2 = (4 *  512 * 2 + 8 * 5 * 4 * 128) * 4;   //  98304 B

    auto* k1 = gemv_fused_kernel<16384, 1024, 4, 8, 5, 8192, true>;
    auto* k2 = gemv_fused_kernel< 8192,  512, 4, 8, 5, 2048, false>;
    cudaFuncSetAttribute(k1, cudaFuncAttributeMaxDynamicSharedMemorySize, SMEM1);
    cudaFuncSetAttribute(k2, cudaFuncAttributeMaxDynamicSharedMemorySize, SMEM2);

    // Kernel 1: g_hidden = tanh(x@Wx^T + h0@Wh^T + b).
    // KC=1024 (16 splits); 256 row tiles of 32 rows -> grid (256,16), occ 2.
    k1<<<dim3(256, 16), 256, SMEM1>>>(w_i2h, x, h0, 8192, b_i2h, nullptr);

    // Kernel 2: out = g_hidden@Wo^T + b.
    // KC=512 (16 splits); 64 row tiles of 32 rows -> grid (64,16) = 1024 blocks
    // (fine work quanta flatten the partial-wave tail).
    k2<<<dim3(64, 16), 256, SMEM2>>>(w_h2o, nullptr, x /*unused: splitK==KFULL*/,
                                     8192, b_h2o, out);

    (void)in_sizes; (void)n_in; (void)out_size;
}

// round 16
// speedup vs baseline: 1.1233x; 1.1233x over previous
#include <cuda_runtime.h>

#define BATCH 8
typedef unsigned long long ull;

// Inter-kernel scratch (no allocations allowed). These symbols are ONLY
// referenced from device code — passing a __device__ symbol as a host-side
// kernel argument yields the host shadow address (the R5 bug).
__device__ float g_hidden[BATCH * 8192];             // [batch][8192]
__device__ float g_part[16 * BATCH * 8192];          // [split][batch][row], 4 MB
__device__ int   g_ctr1[512];                         // k1 per-row-tile arrival counters
__device__ int   g_ctr2[128];                         // k2 per-row-tile arrival counters

__device__ __forceinline__ void fma2(ull &acc, ull a, ull b) {
    // packed fp32x2 FMA (Blackwell): acc.lo += a.lo*b.lo; acc.hi += a.hi*b.hi
    asm volatile("fma.rn.f32x2 %0, %1, %2, %0;" : "+l"(acc) : "l"(a), "l"(b));
}

// duplicate one fp32 into both halves of an f32x2 register pair
__device__ __forceinline__ ull dupf(unsigned w) {
    ull d;
    asm("mov.b64 %0, {%1, %1};" : "=l"(d) : "r"(w));
    return d;
}

// 1-bit XOR swizzle: makes the mainloop's 32B-strided LDS.128 input pattern
// conflict-free (each 8-lane phase covers all 32 banks). 16B-granular.
__device__ __forceinline__ int swz(int off) {
    return off ^ ((off >> 3) & 0x10);
}

// Split-K GEMV. Mainloop has ZERO block-wide barriers. The warp's ENTIRE
// KC-chunk of weights (STEPS stages x RPW rows x 16B/lane) is front-batched
// into registers BEFORE input staging: ~8 KB per warp posted in one burst,
// 16 warps/SM -> ~128 KB in flight, far above the BW-latency product. With
// RPW=2 the register cost fits: 8 stages x 2 rows x uint4 = 64 regs.
//   acc[r][p] = f32x2 accumulator for (row r, batches 2p/2p+1).
//   partial[(y*BATCH+b)*ROWS + row] = sum_{k in split y} W[row,k]*in[b,k]
//   Last arriving split block per row tile sums partials in fixed order
//   (deterministic), adds bias, optional tanh, writes dst[b*ROWS + row].
// in = concat(inA [BATCH, splitK], inB [BATCH, KFULL-splitK]); inA==nullptr -> g_hidden.
// Grid: x = row tiles (ROWS/(RPW*WARPS)), y = split, SPLITS = KFULL/KC.
template<int KFULL, int KC, int RPW, int WARPS, int ROWS, bool TANH>
__global__ void __launch_bounds__(WARPS * 32, 2) gemv_fused_kernel(
    const float* __restrict__ W,
    const float* __restrict__ inA,
    const float* __restrict__ inB,
    int splitK,
    const float* __restrict__ bias,
    float* __restrict__ outArg)
{
    constexpr int RPB    = RPW * WARPS;            // rows per block
    constexpr int SPLITS = KFULL / KC;
    constexpr int STEPS  = KC / 128;               // 128 k per warp per step
    constexpr int NPAIR  = BATCH / 2;              // 4 batch pairs
    static_assert(RPB * BATCH <= WARPS * 32, "epilogue threads");

    // Pair-interleaved inputs: s_in[p][k][0]=in[2p][k], [1]=in[2p+1][k].
    __shared__ float s_in[NPAIR][KC][2];
    __shared__ int s_last;

    const int tid  = threadIdx.x;
    const int lane = tid & 31;
    const int warp = tid >> 5;
    const int row0 = blockIdx.x * RPB + warp * RPW;
    const int koff = blockIdx.y * KC;

    const float* srcA = inA ? inA : (const float*)g_hidden;

    // ---- FRONT-BATCH all weight LDGs for this warp's whole KC chunk ----
    // Issued before input staging so DRAM latency overlaps the staging reads.
    // lane owns 4 CONSECUTIVE k: coalesced LDG.128, contiguous 512B/row/warp.
    const float* wsrc = W + (size_t)row0 * KFULL + koff + lane * 4;
    uint4 wbuf[STEPS][RPW];
    #pragma unroll
    for (int s = 0; s < STEPS; s++)
        #pragma unroll
        for (int r = 0; r < RPW; r++)
            wbuf[s][r] = __ldcs((const uint4*)(wsrc + (size_t)r * KFULL + s * 128));

    // ---- One-time input staging: LDG two batch rows, STS interleaved ----
    {
        constexpr int NU = NPAIR * (KC / 4);       // units of (pair, 4 k)
        char* sbytes = (char*)&s_in[0][0][0];
        #pragma unroll
        for (int u = tid; u < NU; u += WARPS * 32) {
            int p  = u / (KC / 4);
            int kl = (u % (KC / 4)) * 4;           // local k, 4-aligned
            int kg = koff + kl;
            const float* s0;
            const float* s1;
            if (kg < splitK) {
                s0 = srcA + (size_t)(2 * p)     * splitK + kg;
                s1 = srcA + (size_t)(2 * p + 1) * splitK + kg;
            } else {
                s0 = inB + (size_t)(2 * p)     * (KFULL - splitK) + (kg - splitK);
                s1 = inB + (size_t)(2 * p + 1) * (KFULL - splitK) + (kg - splitK);
            }
            float4 a = *(const float4*)s0;
            float4 b = *(const float4*)s1;
            char* base = sbytes + (size_t)p * (KC * 8);
            *(float4*)(base + swz(kl * 8))      = make_float4(a.x, b.x, a.y, b.y);
            *(float4*)(base + swz(kl * 8 + 16)) = make_float4(a.z, b.z, a.w, b.w);
        }
        __syncthreads();                           // the only block-wide barrier
    }

    // ---- Barrier-free mainloop: consume register stages in order ----
    ull acc[RPW][NPAIR];
    #pragma unroll
    for (int r = 0; r < RPW; r++)
        #pragma unroll
        for (int p = 0; p < NPAIR; p++)
            acc[r][p] = 0ull;

    const char* sbytes = (const char*)&s_in[0][0][0];

    #pragma unroll
    for (int s = 0; s < STEPS; s++) {
        const int kk = s * 128 + lane * 4;         // element index of lane's k0
        // broadcast each weight into both f32x2 halves (hoisted: 8 movs/step)
        ull d[RPW][4];
        #pragma unroll
        for (int r = 0; r < RPW; r++) {
            d[r][0] = dupf(wbuf[s][r].x);
            d[r][1] = dupf(wbuf[s][r].y);
            d[r][2] = dupf(wbuf[s][r].z);
            d[r][3] = dupf(wbuf[s][r].w);
        }
        #pragma unroll
        for (int p = 0; p < NPAIR; p++) {          // p outer: iv liveness = 8 regs
            const char* base = sbytes + (size_t)p * (KC * 8);
            ulonglong2 ivA = *(const ulonglong2*)(base + swz(kk * 8));      // k0,k1
            ulonglong2 ivB = *(const ulonglong2*)(base + swz(kk * 8 + 16)); // k2,k3
            #pragma unroll
            for (int r = 0; r < RPW; r++) {
                fma2(acc[r][p], d[r][0], ivA.x);
                fma2(acc[r][p], d[r][1], ivA.y);
                fma2(acc[r][p], d[r][2], ivB.x);
                fma2(acc[r][p], d[r][3], ivB.y);
            }
        }
    }

    // Cross-lane reduce: lane (r*8+b) ends owning partial (row0+r, batch b).
    float myval = 0.f;
    #pragma unroll
    for (int r = 0; r < RPW; r++) {
        #pragma unroll
        for (int b = 0; b < BATCH; b++) {
            ull a = acc[r][b >> 1];
            float v = (b & 1) ? __uint_as_float((unsigned)(a >> 32))
                              : __uint_as_float((unsigned)(a & 0xffffffffu));
            #pragma unroll
            for (int off = 16; off; off >>= 1)
                v += __shfl_xor_sync(0xffffffffu, v, off);
            if (lane == r * BATCH + b) myval = v;
        }
    }
    if (lane < RPW * BATCH) {
        const int r   = lane / BATCH;
        const int b   = lane % BATCH;
        const int row = row0 + r;
        g_part[((size_t)blockIdx.y * BATCH + b) * ROWS + row] = myval;
    }

    // ---- Fused epilogue: last split block for this row tile finishes the sum ----
    __threadfence();          // release: make this block's partials visible
    __syncthreads();          // all partials of this block written before the count
    int* ctr = TANH ? g_ctr1 : g_ctr2;
    if (tid == 0) {
        int old = atomicAdd(&ctr[blockIdx.x], 1);
        s_last = (old == SPLITS - 1);
    }
    __syncthreads();
    if (s_last && tid < RPB * BATCH) {
        __threadfence();      // acquire: see all other splits' partials
        // thread tid -> (row = base + tid/8, batch = tid%8)
        const int r   = tid >> 3;
        const int b   = tid & 7;
        const int row = blockIdx.x * RPB + r;
        float v = bias[row];
        #pragma unroll
        for (int s = 0; s < SPLITS; s++)              // fixed order -> deterministic
            v += g_part[((size_t)s * BATCH + b) * ROWS + row];
        if (TANH) v = tanhf(v);
        float* dst = TANH ? (float*)g_hidden : outArg;
        dst[(size_t)b * ROWS + row] = v;
        if (tid == 0) ctr[blockIdx.x] = 0;            // reset for next graph replay
    }
}

extern "C" void kernel_launch(void* const* d_in, const int* in_sizes, int n_in,
                              void* d_out, int out_size) {
    const float* x     = (const float*)d_in[0];   // [8, 8192]
    const float* h0    = (const float*)d_in[1];   // [8, 8192]
    const float* w_i2h = (const float*)d_in[2];   // [8192, 16384]
    const float* b_i2h = (const float*)d_in[3];   // [8192]
    const float* w_h2o = (const float*)d_in[4];   // [2048, 8192]
    const float* b_h2o = (const float*)d_in[5];   // [2048]
    float* out = (float*)d_out;                   // [8, 2048]

    // Kernel 1: g_hidden = tanh(x@Wx^T + h0@Wh^T + b).
    // KC=1024 (16 splits), 16 rows/block -> grid (512,16), 256 thr, occ 2.
    // 8 register stages = full-chunk weight front-batch (8 KB/warp in flight).
    gemv_fused_kernel<16384, 1024, 2, 8, 8192, true><<<dim3(512, 16), 256>>>(
        w_i2h, x, h0, 8192, b_i2h, nullptr);

    // Kernel 2: out = g_hidden@Wo^T + b.
    // KC=512 (16 splits), 16 rows/block -> grid (128,16) = 2048 blocks
    // (fine quanta flatten the tail; 4 register stages = 4 KB/warp).
    gemv_fused_kernel<8192, 512, 2, 8, 2048, false><<<dim3(128, 16), 256>>>(
        w_h2o, nullptr, x /*unused: splitK==KFULL*/, 8192, b_h2o, out);

    (void)in_sizes; (void)n_in; (void)out_size;
}